// round 2
// baseline (speedup 1.0000x reference)
#include <cuda_runtime.h>
#include <math.h>

#define NN 50000
#define NE 800000
#define DD 64
#define GG 512
#define CHUNK 512
#define NCHUNK ((NN + CHUNK - 1) / CHUNK)   // 98

// -------- scratch (device globals; no allocation allowed) --------
__device__ float g_bufA[NN * DD];
__device__ float g_bufB[NN * DD];
__device__ float g_agg[NN * DD];
__device__ int   g_cnt[NN];
__device__ int   g_rowptr[NN + 1];
__device__ int   g_cursor[NN];
__device__ int   g_csr[NE];
__device__ int   g_chunksum[NCHUNK];
__device__ float g_pool[GG * DD];
__device__ float g_pcnt[GG];

__device__ __forceinline__ const float* pick_in(int sel, const float* x) {
    return sel == 0 ? x : (sel == 1 ? g_bufA : g_bufB);
}

// -------- CSR build --------
__global__ void k_zero() {
    int i = blockIdx.x * blockDim.x + threadIdx.x;
    if (i < NN) g_cnt[i] = 0;
    if (i < GG) g_pcnt[i] = 0.f;
    if (i < GG * DD) g_pool[i] = 0.f;
}

__global__ void k_count(const int* __restrict__ dst) {
    int e = blockIdx.x * blockDim.x + threadIdx.x;
    if (e < NE) atomicAdd(&g_cnt[dst[e]], 1);
}

__global__ void k_scan1() {
    __shared__ int s[CHUNK];
    int i = blockIdx.x * CHUNK + threadIdx.x;
    s[threadIdx.x] = (i < NN) ? g_cnt[i] : 0;
    __syncthreads();
    for (int off = CHUNK / 2; off > 0; off >>= 1) {
        if (threadIdx.x < off) s[threadIdx.x] += s[threadIdx.x + off];
        __syncthreads();
    }
    if (threadIdx.x == 0) g_chunksum[blockIdx.x] = s[0];
}

// parallel exclusive scan over the 98 chunk sums (single block)
__global__ void k_scan2() {
    __shared__ int s[128];
    int i = threadIdx.x;
    int v = (i < NCHUNK) ? g_chunksum[i] : 0;
    s[i] = v;
    __syncthreads();
    for (int off = 1; off < 128; off <<= 1) {
        int t = (i >= off) ? s[i - off] : 0;
        __syncthreads();
        s[i] += t;
        __syncthreads();
    }
    if (i < NCHUNK) g_chunksum[i] = s[i] - v;   // exclusive
    if (i == 0) g_rowptr[NN] = NE;
}

__global__ void k_scan3(const int* __restrict__ batch) {
    __shared__ int s[CHUNK];
    int i = blockIdx.x * CHUNK + threadIdx.x;
    int v = (i < NN) ? g_cnt[i] : 0;
    s[threadIdx.x] = v;
    __syncthreads();
    for (int off = 1; off < CHUNK; off <<= 1) {
        int t = (threadIdx.x >= off) ? s[threadIdx.x - off] : 0;
        __syncthreads();
        s[threadIdx.x] += t;
        __syncthreads();
    }
    if (i < NN) {
        int excl = g_chunksum[blockIdx.x] + s[threadIdx.x] - v;
        g_rowptr[i] = excl;
        g_cursor[i] = excl;
        atomicAdd(&g_pcnt[batch[i]], 1.f);
    }
}

__global__ void k_fill(const int* __restrict__ src, const int* __restrict__ dst) {
    int e = blockIdx.x * blockDim.x + threadIdx.x;
    if (e < NE) {
        int pos = atomicAdd(&g_cursor[dst[e]], 1);
        g_csr[pos] = src[e];
    }
}

// -------- per-layer edge aggregation: agg[i] = sum_{j in N(i)} h[j] --------
// 4 nodes per 256-thread block, 64 threads per node (coalesced 256B rows).
// 4-way edge unroll with independent accumulators -> MLP=4 on the L2 path.
__global__ void k_agg(const float* __restrict__ x, int sel) {
    const float* h = pick_in(sel, x);
    int node = blockIdx.x * 4 + (threadIdx.x >> 6);
    int d = threadIdx.x & 63;
    if (node >= NN) return;
    int s0 = g_rowptr[node];
    int s1 = g_rowptr[node + 1];
    float a0 = 0.f, a1 = 0.f, a2 = 0.f, a3 = 0.f;
    int e = s0;
    int e4 = s0 + ((s1 - s0) & ~3);
    for (; e < e4; e += 4) {
        int i0 = __ldg(&g_csr[e + 0]);
        int i1 = __ldg(&g_csr[e + 1]);
        int i2 = __ldg(&g_csr[e + 2]);
        int i3 = __ldg(&g_csr[e + 3]);
        a0 += __ldg(&h[i0 * DD + d]);
        a1 += __ldg(&h[i1 * DD + d]);
        a2 += __ldg(&h[i2 * DD + d]);
        a3 += __ldg(&h[i3 * DD + d]);
    }
    for (; e < s1; e++) a0 += __ldg(&h[__ldg(&g_csr[e]) * DD + d]);
    g_agg[node * DD + d] = (a0 + a1) + (a2 + a3);
}

// -------- fused layer GEMM with packed fp32 (fma.rn.f32x2) ----------------
// out = relu(agg@Wrel^T + b + h@Wroot^T (+ h))   [+ optional pool atomics]
// 64 nodes x 64 outputs per block, 128 threads, 4x8 register tile per thread.
// K-major staging with stride 68 (16B-aligned rows, conflict-light).
#define STRIDE 68
__global__ void __launch_bounds__(128)
k_gemm(const float* __restrict__ x, int insel, int outsel,
       const float* __restrict__ wrel,
       const float* __restrict__ wroot,
       const float* __restrict__ brel,
       int residual, int dopool, const int* __restrict__ batch) {
    const float* hin = pick_in(insel, x);
    float* hout = (outsel == 1) ? g_bufA : g_bufB;

    __shared__ float As[64 * STRIDE];
    __shared__ float Bs[64 * STRIDE];

    int tid = threadIdx.x;
    int tx = tid & 7;          // 8 output cols: j = tx*8 + c
    int ty = tid >> 3;         // 4 node rows: m = ty*4 + i
    int m0 = blockIdx.x * 64;

    unsigned long long acc2[4][4];   // [row][col-pair], each = 2 packed fp32
#pragma unroll
    for (int i = 0; i < 4; i++)
#pragma unroll
        for (int p = 0; p < 4; p++) acc2[i][p] = 0ULL;

#pragma unroll
    for (int phase = 0; phase < 2; phase++) {
        const float* A = phase ? hin : g_agg;
        const float* W = phase ? wroot : wrel;
        if (phase) __syncthreads();   // protect As/Bs before restage

        // stage: As[k][m] = A[m0+m][k] ; Bs[k][j] = W[j][k]
#pragma unroll
        for (int it = 0; it < 8; it++) {
            int lin = it * 128 + tid;
            int kq = lin & 15;        // k quad (4 floats)
            int mm = lin >> 4;        // 0..63
            float4 v = make_float4(0.f, 0.f, 0.f, 0.f);
            if (m0 + mm < NN) v = *(const float4*)&A[(m0 + mm) * DD + kq * 4];
            As[(kq * 4 + 0) * STRIDE + mm] = v.x;
            As[(kq * 4 + 1) * STRIDE + mm] = v.y;
            As[(kq * 4 + 2) * STRIDE + mm] = v.z;
            As[(kq * 4 + 3) * STRIDE + mm] = v.w;
            float4 w = *(const float4*)&W[mm * DD + kq * 4];
            Bs[(kq * 4 + 0) * STRIDE + mm] = w.x;
            Bs[(kq * 4 + 1) * STRIDE + mm] = w.y;
            Bs[(kq * 4 + 2) * STRIDE + mm] = w.z;
            Bs[(kq * 4 + 3) * STRIDE + mm] = w.w;
        }
        __syncthreads();

#pragma unroll
        for (int k = 0; k < 64; k++) {
            float4 a = *(const float4*)&As[k * STRIDE + ty * 4];
            ulonglong2 b0 = *(const ulonglong2*)&Bs[k * STRIDE + tx * 8];
            ulonglong2 b1 = *(const ulonglong2*)&Bs[k * STRIDE + tx * 8 + 4];
            float av[4] = {a.x, a.y, a.z, a.w};
            unsigned long long bv[4] = {b0.x, b0.y, b1.x, b1.y};
#pragma unroll
            for (int i = 0; i < 4; i++) {
                unsigned long long ad;
                asm("mov.b64 %0, {%1, %2};" : "=l"(ad) : "f"(av[i]), "f"(av[i]));
#pragma unroll
                for (int p = 0; p < 4; p++)
                    asm("fma.rn.f32x2 %0, %1, %2, %0;"
                        : "+l"(acc2[i][p]) : "l"(ad), "l"(bv[p]));
            }
        }
        // after phase 1, As still holds hin (k-major) for the residual read
    }

    float bias[8];
#pragma unroll
    for (int c = 0; c < 8; c++) bias[c] = __ldg(&brel[tx * 8 + c]);

#pragma unroll
    for (int i = 0; i < 4; i++) {
        int m = m0 + ty * 4 + i;
        if (m >= NN) continue;
        float v[8];
#pragma unroll
        for (int p = 0; p < 4; p++) {
            float lo, hi;
            asm("mov.b64 {%0, %1}, %2;" : "=f"(lo), "=f"(hi) : "l"(acc2[i][p]));
            v[2 * p]     = lo;
            v[2 * p + 1] = hi;
        }
#pragma unroll
        for (int c = 0; c < 8; c++) v[c] += bias[c];
        if (residual) {
#pragma unroll
            for (int c = 0; c < 8; c++)
                v[c] += As[(tx * 8 + c) * STRIDE + (ty * 4 + i)];
        }
#pragma unroll
        for (int c = 0; c < 8; c++) v[c] = fmaxf(v[c], 0.f);

        if (dopool) {
            int b = __ldg(&batch[m]);
#pragma unroll
            for (int c = 0; c < 8; c++)
                atomicAdd(&g_pool[b * DD + tx * 8 + c], v[c]);
        } else {
            float4 r0 = make_float4(v[0], v[1], v[2], v[3]);
            float4 r1 = make_float4(v[4], v[5], v[6], v[7]);
            *(float4*)&hout[m * DD + tx * 8]     = r0;
            *(float4*)&hout[m * DD + tx * 8 + 4] = r1;
        }
    }
}

// -------- final linear + softmax, one block per graph --------
__global__ void k_final(const float* __restrict__ lin_w,
                        const float* __restrict__ lin_b,
                        float* __restrict__ out) {
    __shared__ float sw[64 * 65];
    __shared__ float p[64];
    __shared__ float red[64];
    int g = blockIdx.x;
    int j = threadIdx.x;

    for (int r = 0; r < 64; r++) sw[j * 65 + r] = lin_w[r * 64 + j];

    float cnt = fmaxf(g_pcnt[g], 1.f);
    p[j] = g_pool[g * DD + j] / cnt;
    __syncthreads();

    float acc = lin_b[j];
#pragma unroll
    for (int k = 0; k < 64; k++) acc += p[k] * sw[k * 65 + j];

    red[j] = acc;
    __syncthreads();
    for (int s = 32; s > 0; s >>= 1) {
        if (j < s) red[j] = fmaxf(red[j], red[j + s]);
        __syncthreads();
    }
    float mx = red[0];
    __syncthreads();
    float e = expf(acc - mx);
    red[j] = e;
    __syncthreads();
    for (int s = 32; s > 0; s >>= 1) {
        if (j < s) red[j] += red[j + s];
        __syncthreads();
    }
    out[g * DD + j] = e / red[0];
}

extern "C" void kernel_launch(void* const* d_in, const int* in_sizes, int n_in,
                              void* d_out, int out_size) {
    const float* x      = (const float*)d_in[0];
    const int*   ei     = (const int*)d_in[1];
    const int*   batch  = (const int*)d_in[2];
    const float* rel_w  = (const float*)d_in[3];
    const float* rel_b  = (const float*)d_in[4];
    const float* root_w = (const float*)d_in[5];
    const float* lin_w  = (const float*)d_in[6];
    const float* lin_b  = (const float*)d_in[7];
    float* out = (float*)d_out;

    const int* src = ei;
    const int* dst = ei + NE;

    k_zero<<<(NN + 255) / 256, 256>>>();
    k_count<<<(NE + 255) / 256, 256>>>(dst);
    k_scan1<<<NCHUNK, CHUNK>>>();
    k_scan2<<<1, 128>>>();
    k_scan3<<<NCHUNK, CHUNK>>>(batch);
    k_fill<<<(NE + 255) / 256, 256>>>(src, dst);

    int insel = 0;
    for (int l = 0; l < 5; l++) {
        int outsel = (insel == 1) ? 2 : 1;
        k_agg<<<(NN + 3) / 4, 256>>>(x, insel);
        k_gemm<<<(NN + 63) / 64, 128>>>(x, insel, outsel,
                                        rel_w + l * DD * DD,
                                        root_w + l * DD * DD,
                                        rel_b + l * DD,
                                        (l >= 3) ? 1 : 0,
                                        (l == 4) ? 1 : 0,
                                        batch);
        insel = outsel;
    }

    k_final<<<GG, DD>>>(lin_w, lin_b, out);
}

// round 3
// speedup vs baseline: 1.3777x; 1.3777x over previous
#include <cuda_runtime.h>
#include <math.h>

#define NN 50000
#define NE 800000
#define DD 64
#define GG 512
#define CHUNK 512
#define NCHUNK ((NN + CHUNK - 1) / CHUNK)   // 98

// -------- scratch (device globals; no allocation allowed) --------
__device__ float g_bufA[NN * DD];
__device__ float g_bufB[NN * DD];
__device__ float g_agg[NN * DD];
__device__ int   g_cnt[NN];
__device__ int   g_rowptr[NN + 1];
__device__ int   g_cursor[NN];
__device__ int   g_csr[NE];
__device__ int   g_chunksum[NCHUNK];
__device__ float g_pool[GG * DD];
__device__ float g_pcnt[GG];

__device__ __forceinline__ const float* pick_in(int sel, const float* x) {
    return sel == 0 ? x : (sel == 1 ? g_bufA : g_bufB);
}

// -------- CSR build --------
__global__ void k_zero() {
    int i = blockIdx.x * blockDim.x + threadIdx.x;
    if (i < NN) g_cnt[i] = 0;
    if (i < GG) g_pcnt[i] = 0.f;
    if (i < GG * DD) g_pool[i] = 0.f;
}

__global__ void k_count(const int* __restrict__ dst) {
    int e = blockIdx.x * blockDim.x + threadIdx.x;
    if (e < NE) atomicAdd(&g_cnt[dst[e]], 1);
}

__global__ void k_scan1() {
    __shared__ int s[CHUNK];
    int i = blockIdx.x * CHUNK + threadIdx.x;
    s[threadIdx.x] = (i < NN) ? g_cnt[i] : 0;
    __syncthreads();
    for (int off = CHUNK / 2; off > 0; off >>= 1) {
        if (threadIdx.x < off) s[threadIdx.x] += s[threadIdx.x + off];
        __syncthreads();
    }
    if (threadIdx.x == 0) g_chunksum[blockIdx.x] = s[0];
}

// parallel exclusive scan over the 98 chunk sums (single block)
__global__ void k_scan2() {
    __shared__ int s[128];
    int i = threadIdx.x;
    int v = (i < NCHUNK) ? g_chunksum[i] : 0;
    s[i] = v;
    __syncthreads();
    for (int off = 1; off < 128; off <<= 1) {
        int t = (i >= off) ? s[i - off] : 0;
        __syncthreads();
        s[i] += t;
        __syncthreads();
    }
    if (i < NCHUNK) g_chunksum[i] = s[i] - v;   // exclusive
    if (i == 0) g_rowptr[NN] = NE;
}

__global__ void k_scan3(const int* __restrict__ batch) {
    __shared__ int s[CHUNK];
    int i = blockIdx.x * CHUNK + threadIdx.x;
    int v = (i < NN) ? g_cnt[i] : 0;
    s[threadIdx.x] = v;
    __syncthreads();
    for (int off = 1; off < CHUNK; off <<= 1) {
        int t = (threadIdx.x >= off) ? s[threadIdx.x - off] : 0;
        __syncthreads();
        s[threadIdx.x] += t;
        __syncthreads();
    }
    if (i < NN) {
        int excl = g_chunksum[blockIdx.x] + s[threadIdx.x] - v;
        g_rowptr[i] = excl;
        g_cursor[i] = excl;
        atomicAdd(&g_pcnt[batch[i]], 1.f);
    }
}

__global__ void k_fill(const int* __restrict__ src, const int* __restrict__ dst) {
    int e = blockIdx.x * blockDim.x + threadIdx.x;
    if (e < NE) {
        int pos = atomicAdd(&g_cursor[dst[e]], 1);
        g_csr[pos] = src[e];
    }
}

// -------- per-layer edge aggregation: agg[i] = sum_{j in N(i)} h[j] --------
// 16 threads per node, each owning one float4 of the 64-float row (LDG.128).
// 4-edge unroll with independent float4 accumulators -> MLP=4 on the L2 path.
__global__ void k_agg(const float* __restrict__ x, int sel) {
    const float* h = pick_in(sel, x);
    int node = blockIdx.x * 16 + (threadIdx.x >> 4);
    int q = threadIdx.x & 15;          // float4 index within row
    if (node >= NN) return;
    int s0 = g_rowptr[node];
    int s1 = g_rowptr[node + 1];
    float4 a0 = make_float4(0.f, 0.f, 0.f, 0.f);
    float4 a1 = a0, a2 = a0, a3 = a0;
    int e = s0;
    int e4 = s0 + ((s1 - s0) & ~3);
    for (; e < e4; e += 4) {
        int i0 = __ldg(&g_csr[e + 0]);
        int i1 = __ldg(&g_csr[e + 1]);
        int i2 = __ldg(&g_csr[e + 2]);
        int i3 = __ldg(&g_csr[e + 3]);
        float4 v0 = __ldg((const float4*)&h[i0 * DD + q * 4]);
        float4 v1 = __ldg((const float4*)&h[i1 * DD + q * 4]);
        float4 v2 = __ldg((const float4*)&h[i2 * DD + q * 4]);
        float4 v3 = __ldg((const float4*)&h[i3 * DD + q * 4]);
        a0.x += v0.x; a0.y += v0.y; a0.z += v0.z; a0.w += v0.w;
        a1.x += v1.x; a1.y += v1.y; a1.z += v1.z; a1.w += v1.w;
        a2.x += v2.x; a2.y += v2.y; a2.z += v2.z; a2.w += v2.w;
        a3.x += v3.x; a3.y += v3.y; a3.z += v3.z; a3.w += v3.w;
    }
    for (; e < s1; e++) {
        int i0 = __ldg(&g_csr[e]);
        float4 v0 = __ldg((const float4*)&h[i0 * DD + q * 4]);
        a0.x += v0.x; a0.y += v0.y; a0.z += v0.z; a0.w += v0.w;
    }
    float4 r;
    r.x = (a0.x + a1.x) + (a2.x + a3.x);
    r.y = (a0.y + a1.y) + (a2.y + a3.y);
    r.z = (a0.z + a1.z) + (a2.z + a3.z);
    r.w = (a0.w + a1.w) + (a2.w + a3.w);
    *(float4*)&g_agg[node * DD + q * 4] = r;
}

// -------- fused layer GEMM: out = relu(agg@Wrel^T + b + h@Wroot^T (+ h)) ----
// (round-1 proven form: 256 threads, 64x64 tile, 4x4 register tile, XOR swizzle)
__global__ void k_gemm(const float* __restrict__ x, int insel, int outsel,
                       const float* __restrict__ wrel,
                       const float* __restrict__ wroot,
                       const float* __restrict__ brel,
                       int residual, int dopool, const int* __restrict__ batch) {
    const float* hin = pick_in(insel, x);
    float* hout = (outsel == 1) ? g_bufA : g_bufB;

    __shared__ float As[64 * 64];
    __shared__ float Bs[64 * 64];

    int tid = threadIdx.x;
    int tx = tid & 15;        // output group (4 cols)
    int ty = tid >> 4;        // node group (4 rows)
    int m0 = blockIdx.x * 64;

    float acc[4][4];
#pragma unroll
    for (int i = 0; i < 4; i++)
#pragma unroll
        for (int j = 0; j < 4; j++) acc[i][j] = 0.f;

#pragma unroll
    for (int phase = 0; phase < 2; phase++) {
        const float* A = phase ? hin : g_agg;
        const float* W = phase ? wroot : wrel;

        // stage A tile (transpose to k-major, swizzled)
#pragma unroll
        for (int it = 0; it < 4; it++) {
            int m = it * 16 + ty;
            int kq = tx;
            float4 v = make_float4(0.f, 0.f, 0.f, 0.f);
            if (m0 + m < NN) v = *(const float4*)&A[(m0 + m) * DD + kq * 4];
            int col = ((((m >> 2) ^ kq) & 15) << 2) | (m & 3);
            As[(kq * 4 + 0) * 64 + col] = v.x;
            As[(kq * 4 + 1) * 64 + col] = v.y;
            As[(kq * 4 + 2) * 64 + col] = v.z;
            As[(kq * 4 + 3) * 64 + col] = v.w;
        }
        // stage B tile: Bs[k][j] = W[j][k]
#pragma unroll
        for (int it = 0; it < 4; it++) {
            int j = it * 16 + ty;
            int kq = tx;
            float4 v = *(const float4*)&W[j * DD + kq * 4];
            int col = ((((j >> 2) ^ kq) & 15) << 2) | (j & 3);
            Bs[(kq * 4 + 0) * 64 + col] = v.x;
            Bs[(kq * 4 + 1) * 64 + col] = v.y;
            Bs[(kq * 4 + 2) * 64 + col] = v.z;
            Bs[(kq * 4 + 3) * 64 + col] = v.w;
        }
        __syncthreads();

#pragma unroll
        for (int k = 0; k < 64; k++) {
            int sw = (k >> 2) & 15;
            float4 a = *(const float4*)&As[k * 64 + ((ty ^ sw) << 2)];
            float4 b = *(const float4*)&Bs[k * 64 + ((tx ^ sw) << 2)];
            float av[4] = {a.x, a.y, a.z, a.w};
            float bv[4] = {b.x, b.y, b.z, b.w};
#pragma unroll
            for (int i = 0; i < 4; i++)
#pragma unroll
                for (int j = 0; j < 4; j++) acc[i][j] += av[i] * bv[j];
        }
        __syncthreads();
    }

    float bias[4];
#pragma unroll
    for (int jj = 0; jj < 4; jj++) bias[jj] = __ldg(&brel[tx * 4 + jj]);

#pragma unroll
    for (int i = 0; i < 4; i++) {
        int m = m0 + ty * 4 + i;
        if (m >= NN) continue;
        float v0 = acc[i][0] + bias[0];
        float v1 = acc[i][1] + bias[1];
        float v2 = acc[i][2] + bias[2];
        float v3 = acc[i][3] + bias[3];
        if (residual) {
            float4 h4 = *(const float4*)&hin[m * DD + tx * 4];
            v0 += h4.x; v1 += h4.y; v2 += h4.z; v3 += h4.w;
        }
        v0 = fmaxf(v0, 0.f);
        v1 = fmaxf(v1, 0.f);
        v2 = fmaxf(v2, 0.f);
        v3 = fmaxf(v3, 0.f);
        if (dopool) {
            int b = __ldg(&batch[m]);
            atomicAdd(&g_pool[b * DD + tx * 4 + 0], v0);
            atomicAdd(&g_pool[b * DD + tx * 4 + 1], v1);
            atomicAdd(&g_pool[b * DD + tx * 4 + 2], v2);
            atomicAdd(&g_pool[b * DD + tx * 4 + 3], v3);
        } else {
            float4 r = make_float4(v0, v1, v2, v3);
            *(float4*)&hout[m * DD + tx * 4] = r;
        }
    }
}

// -------- final linear + softmax, one block per graph --------
__global__ void k_final(const float* __restrict__ lin_w,
                        const float* __restrict__ lin_b,
                        float* __restrict__ out) {
    __shared__ float sw[64 * 65];
    __shared__ float p[64];
    __shared__ float red[64];
    int g = blockIdx.x;
    int j = threadIdx.x;

    for (int r = 0; r < 64; r++) sw[j * 65 + r] = lin_w[r * 64 + j];

    float cnt = fmaxf(g_pcnt[g], 1.f);
    p[j] = g_pool[g * DD + j] / cnt;
    __syncthreads();

    float acc = lin_b[j];
#pragma unroll
    for (int k = 0; k < 64; k++) acc += p[k] * sw[k * 65 + j];

    red[j] = acc;
    __syncthreads();
    for (int s = 32; s > 0; s >>= 1) {
        if (j < s) red[j] = fmaxf(red[j], red[j + s]);
        __syncthreads();
    }
    float mx = red[0];
    __syncthreads();
    float e = expf(acc - mx);
    red[j] = e;
    __syncthreads();
    for (int s = 32; s > 0; s >>= 1) {
        if (j < s) red[j] += red[j + s];
        __syncthreads();
    }
    out[g * DD + j] = e / red[0];
}

extern "C" void kernel_launch(void* const* d_in, const int* in_sizes, int n_in,
                              void* d_out, int out_size) {
    const float* x      = (const float*)d_in[0];
    const int*   ei     = (const int*)d_in[1];
    const int*   batch  = (const int*)d_in[2];
    const float* rel_w  = (const float*)d_in[3];
    const float* rel_b  = (const float*)d_in[4];
    const float* root_w = (const float*)d_in[5];
    const float* lin_w  = (const float*)d_in[6];
    const float* lin_b  = (const float*)d_in[7];
    float* out = (float*)d_out;

    const int* src = ei;
    const int* dst = ei + NE;

    k_zero<<<(NN + 255) / 256, 256>>>();
    k_count<<<(NE + 255) / 256, 256>>>(dst);
    k_scan1<<<NCHUNK, CHUNK>>>();
    k_scan2<<<1, 128>>>();
    k_scan3<<<NCHUNK, CHUNK>>>(batch);
    k_fill<<<(NE + 255) / 256, 256>>>(src, dst);

    int insel = 0;
    for (int l = 0; l < 5; l++) {
        int outsel = (insel == 1) ? 2 : 1;
        k_agg<<<(NN + 15) / 16, 256>>>(x, insel);
        k_gemm<<<(NN + 63) / 64, 256>>>(x, insel, outsel,
                                        rel_w + l * DD * DD,
                                        root_w + l * DD * DD,
                                        rel_b + l * DD,
                                        (l >= 3) ? 1 : 0,
                                        (l == 4) ? 1 : 0,
                                        batch);
        insel = outsel;
    }

    k_final<<<GG, DD>>>(lin_w, lin_b, out);
}